// round 15
// baseline (speedup 1.0000x reference)
#include <cuda_runtime.h>
#include <cuda_bf16.h>
#include <cstdint>

#define DD   128
#define TT   4

// ---------------------------------------------------------------------------
// Global scratch
// ---------------------------------------------------------------------------
__device__ float g_E[4L * 25000 * DD];  // per-atom layer-0 partials (51.2 MB)
__device__ int   g_idx64;               // propers dtype flag
__device__ unsigned int g_barrier;      // software grid barrier counter
#define PITCH_B   272                   // 136 bf16 * 2 bytes
#define IMG_BYTES 34816                 // 128 * 272
__device__ __align__(16) unsigned char g_Bimg[4 * IMG_BYTES];    // W1hi,W1lo,W2hi,W2lo
__device__ __align__(16) unsigned char g_B0img[8 * IMG_BYTES];   // W0 chunks 0..3 (hi,lo)

// ---------------------------------------------------------------------------
// helpers
// ---------------------------------------------------------------------------
__device__ __forceinline__ uint32_t pack_split(float v0, float v1, uint32_t& lo_out) {
    __nv_bfloat162 h2 = __floats2bfloat162_rn(v0, v1);
    float r0 = v0 - __bfloat162float(h2.x);
    float r1 = v1 - __bfloat162float(h2.y);
    __nv_bfloat162 l2 = __floats2bfloat162_rn(r0, r1);
    lo_out = *reinterpret_cast<uint32_t*>(&l2);
    return *reinterpret_cast<uint32_t*>(&h2);
}

__device__ __forceinline__ void mma16816(float d[4], const uint32_t a[4],
                                         uint32_t b0, uint32_t b1) {
    asm volatile(
        "mma.sync.aligned.m16n8k16.row.col.f32.bf16.bf16.f32 "
        "{%0,%1,%2,%3}, {%4,%5,%6,%7}, {%8,%9}, {%0,%1,%2,%3};"
        : "+f"(d[0]), "+f"(d[1]), "+f"(d[2]), "+f"(d[3])
        : "r"(a[0]), "r"(a[1]), "r"(a[2]), "r"(a[3]), "r"(b0), "r"(b1));
}

__device__ __forceinline__ void ldm4(uint32_t r[4], uint32_t saddr) {
    asm volatile("ldmatrix.sync.aligned.m8n8.x4.shared.b16 {%0,%1,%2,%3}, [%4];"
        : "=r"(r[0]), "=r"(r[1]), "=r"(r[2]), "=r"(r[3]) : "r"(saddr));
}

__device__ __forceinline__ void load_prop_idx(const void* propers_raw, int is64,
                                              int p, int P, int N, int idx[4]) {
    if (p < P) {
        if (is64) {
            longlong2 a = ((const longlong2*)propers_raw)[(size_t)p * 2];
            longlong2 b = ((const longlong2*)propers_raw)[(size_t)p * 2 + 1];
            idx[0] = (int)a.x; idx[1] = (int)a.y;
            idx[2] = (int)b.x; idx[3] = (int)b.y;
        } else {
            int4 v = ((const int4*)propers_raw)[p];
            idx[0] = v.x; idx[1] = v.y; idx[2] = v.z; idx[3] = v.w;
        }
    } else {
        idx[0] = idx[1] = idx[2] = idx[3] = 0;
    }
    #pragma unroll
    for (int j = 0; j < 4; j++) {
        int v = idx[j];
        v = v < 0 ? 0 : v;
        idx[j] = v >= N ? N - 1 : v;
    }
}

// ---------------------------------------------------------------------------
// merged prep kernel (also zeroes the grid-barrier counter)
// ---------------------------------------------------------------------------
__global__ void prep_all_kernel(const int* __restrict__ prop_words, int nwords,
                                const float* __restrict__ W0,
                                const float* __restrict__ W1,
                                const float* __restrict__ W2)
{
    const int b = blockIdx.x;
    if (b == 0) {
        __shared__ int nz;
        if (threadIdx.x == 0) { nz = 0; g_barrier = 0u; }
        __syncthreads();
        for (int i = 1 + 2 * threadIdx.x; i < nwords; i += 2 * blockDim.x) {
            if (prop_words[i] != 0) { atomicOr(&nz, 1); break; }
        }
        __syncthreads();
        if (threadIdx.x == 0) g_idx64 = (nz == 0) ? 1 : 0;
    } else if (b <= 64) {
        int idx = (b - 1) * 256 + threadIdx.x;
        int l = idx >> 13;
        int r = idx & 8191;
        int n = r >> 6;
        int k = (r & 63) * 2;
        const float* W = l ? W2 : W1;
        float v0 = W[(size_t)k * DD + n];
        float v1 = W[(size_t)(k + 1) * DD + n];
        uint32_t lo, hi = pack_split(v0, v1, lo);
        uint32_t off = (uint32_t)n * PITCH_B + (uint32_t)k * 2;
        *(uint32_t*)(g_Bimg + (l * 2 + 0) * IMG_BYTES + off) = hi;
        *(uint32_t*)(g_Bimg + (l * 2 + 1) * IMG_BYTES + off) = lo;
    } else {
        int idx = (b - 65) * 256 + threadIdx.x;
        int a = idx >> 13;
        int r = idx & 8191;
        int n = r >> 6;
        int k = (r & 63) * 2;
        float v0 = W0[(size_t)(a * 128 + k) * DD + n];
        float v1 = W0[(size_t)(a * 128 + k + 1) * DD + n];
        uint32_t lo, hi = pack_split(v0, v1, lo);
        uint32_t off = (uint32_t)n * PITCH_B + (uint32_t)k * 2;
        *(uint32_t*)(g_B0img + (a * 2 + 0) * IMG_BYTES + off) = hi;
        *(uint32_t*)(g_B0img + (a * 2 + 1) * IMG_BYTES + off) = lo;
    }
}

// ---------------------------------------------------------------------------
// GEMM layer: per warp 32 rows x 32 cols, 3-term bf16 split (R13 form).
// ---------------------------------------------------------------------------
__device__ __forceinline__ void gemm_layer(
    float D[2][4][4],
    uint32_t aHi0, uint32_t aHi1, uint32_t aLo0, uint32_t aLo1,
    uint32_t bHi0, uint32_t bHi1, uint32_t bLo0, uint32_t bLo1)
{
    #pragma unroll
    for (int mt = 0; mt < 2; mt++)
        #pragma unroll
        for (int nt = 0; nt < 4; nt++)
            #pragma unroll
            for (int j = 0; j < 4; j++) D[mt][nt][j] = 0.f;

    #pragma unroll
    for (int ks = 0; ks < 8; ks++) {
        const uint32_t kb = ks * 32;
        uint32_t ah[2][4], al[2][4];
        ldm4(ah[0], aHi0 + kb);
        ldm4(ah[1], aHi1 + kb);
        ldm4(al[0], aLo0 + kb);
        ldm4(al[1], aLo1 + kb);
        #pragma unroll
        for (int ntp = 0; ntp < 2; ntp++) {
            uint32_t bh[4], bl[4];
            ldm4(bh, (ntp ? bHi1 : bHi0) + kb);
            ldm4(bl, (ntp ? bLo1 : bLo0) + kb);
            #pragma unroll
            for (int mt = 0; mt < 2; mt++) {
                #pragma unroll
                for (int sub = 0; sub < 2; sub++) {
                    float* d = D[mt][ntp * 2 + sub];
                    mma16816(d, ah[mt], bh[sub], bh[2 + sub]);
                    mma16816(d, ah[mt], bl[sub], bl[2 + sub]);
                    mma16816(d, al[mt], bh[sub], bh[2 + sub]);
                }
            }
        }
    }
}

// ---------------------------------------------------------------------------
// Fused PERSISTENT kernel:
//   Phase E: compute g_E (2 passes x 2 W0 chunks staged in W_SM), block-
//            cooperative 128-atom tiles, then software grid barrier.
//   Phase P: four independent 4-warp quarter streams over 8-proper tiles
//            (geometry + gather + 2 tcgen-style HMMA layers + scatter).
// ---------------------------------------------------------------------------
#define A_SIZE_Q 8704                      // 32 * 272 (one term, one quarter)
#define W_SM     (8 * A_SIZE_Q)            // 69632
#define E_A_LO_OFF (4 * A_SIZE_Q)          // 34816: lo half of the 128-row A
#define MISC_OFF (W_SM + 4 * IMG_BYTES)    // 208896
#define MISC_FLOATS 3260
#define SMEM_TOTAL (MISC_OFF + MISC_FLOATS * 4)   // 221936

__global__ void __launch_bounds__(512, 1) fused_kernel(
    const float* __restrict__ coords,
    const void* __restrict__ propers_raw,
    const float* __restrict__ t_arr,
    const float* __restrict__ enc,
    const float* __restrict__ W0,
    const float* __restrict__ b0,
    const float* __restrict__ b1,
    const float* __restrict__ b2,
    const float* __restrict__ W3,
    const float* __restrict__ b3,
    float* __restrict__ out,
    int N, int P)
{
    extern __shared__ char smem_raw[];

    float* m    = (float*)(smem_raw + MISC_OFF);
    float* vb1  = m;                // 128
    float* vb2  = m + 128;          // 128
    float* vwt  = m + 256;          // 128
    float* vws  = m + 384;
    float* vwc  = m + 512;
    float* vwd  = m + 640;
    float* vb0  = m + 768;
    float* sW3  = m + 896;          // 256
    float* vb3  = m + 1152;         // 2 (+2 pad)
    float* stv  = m + 1156;         // 4

    const int tid  = threadIdx.x;
    const int w    = tid >> 5;
    const int t    = tid & 31;
    const int q    = w >> 2;          // quarter / row-group 0..3
    const int wc   = w & 3;           // col group (0..3)
    const int tid_q = tid & 127;
    const int is64 = g_idx64;

    // per-quarter misc, parity double-buffered (256 floats per parity)
    float* qmbase = m + 1160 + q * 512;

    // ---- small vectors (misc region; untouched by E phase) ----
    if (tid < 128) {
        vwt[tid] = W0[(size_t)512 * DD + tid];
        vws[tid] = W0[(size_t)513 * DD + tid];
        vwc[tid] = W0[(size_t)514 * DD + tid];
        vwd[tid] = W0[(size_t)515 * DD + tid];
        vb0[tid] = b0[tid];
        vb1[tid] = b1[tid];
        vb2[tid] = b2[tid];
    } else if (tid < 256) {
        int i = tid - 128;
        if (i < 2)  vb3[i] = b3[i];
        if (i < TT) stv[i] = t_arr[i];
    } else if (tid < 512) {
        int i = tid - 256;
        if (i < 256) sW3[i] = W3[i];
    }

    // ---- ldmatrix lane addressing (shared by both phases) ----
    const int lseg = t >> 3;
    const uint32_t lane_off = (uint32_t)((t & 7) + (lseg & 1) * 8) * PITCH_B
                            + (uint32_t)(lseg >> 1) * 16;
    const uint32_t sb = (uint32_t)__cvta_generic_to_shared(smem_raw);

    // ================== PHASE E: per-atom layer-0 partials ==================
    {
        // E-phase A addressing: one 128-row tile in [0, 69632)
        const uint32_t eaHi0 = sb + (uint32_t)(q * 32) * PITCH_B + lane_off;
        const uint32_t eaHi1 = eaHi0 + 16u * PITCH_B;
        const uint32_t eaLo0 = eaHi0 + E_A_LO_OFF;
        const uint32_t eaLo1 = eaHi1 + E_A_LO_OFF;
        const uint32_t ebBase = sb + W_SM + (uint32_t)(wc * 32) * PITCH_B + lane_off;

        const int n_et = (N + 127) >> 7;   // 128-atom tiles

        #pragma unroll 1
        for (int pass = 0; pass < 2; pass++) {
            __syncthreads();   // previous usage of W_SM / A region done
            {
                const float4* src = (const float4*)(g_B0img + (size_t)(pass * 4) * IMG_BYTES);
                float4* dst = (float4*)(smem_raw + W_SM);
                for (int i = tid; i < 4 * IMG_BYTES / 16; i += 512) dst[i] = src[i];
            }
            __syncthreads();

            #pragma unroll 1
            for (int et = blockIdx.x; et < n_et; et += gridDim.x) {
                const int atom0 = et * 128;
                // pack enc tile: 128 rows x 128 cols, split hi/lo
                #pragma unroll
                for (int it = 0; it < 8; it++) {
                    int idx = tid + it * 512;      // 0..4095
                    int row = idx >> 5;
                    int col = (idx & 31) * 4;
                    int atom = atom0 + row;
                    float4 v = make_float4(0.f, 0.f, 0.f, 0.f);
                    if (atom < N) v = *(const float4*)(enc + (size_t)atom * DD + col);
                    uint32_t lo0, hi0 = pack_split(v.x, v.y, lo0);
                    uint32_t lo1, hi1 = pack_split(v.z, v.w, lo1);
                    uint32_t o = (uint32_t)row * PITCH_B + (uint32_t)col * 2;
                    *(uint32_t*)(smem_raw + o)                  = hi0;
                    *(uint32_t*)(smem_raw + o + 4)              = hi1;
                    *(uint32_t*)(smem_raw + E_A_LO_OFF + o)     = lo0;
                    *(uint32_t*)(smem_raw + E_A_LO_OFF + o + 4) = lo1;
                }
                __syncthreads();

                #pragma unroll 1
                for (int c = 0; c < 2; c++) {
                    const int a = pass * 2 + c;
                    const uint32_t bHi0 = ebBase + (uint32_t)(c * 2) * IMG_BYTES;
                    const uint32_t bHi1 = bHi0 + 16u * PITCH_B;
                    const uint32_t bLo0 = bHi0 + IMG_BYTES;
                    const uint32_t bLo1 = bHi1 + IMG_BYTES;

                    float D[2][4][4];
                    gemm_layer(D, eaHi0, eaHi1, eaLo0, eaLo1, bHi0, bHi1, bLo0, bLo1);

                    #pragma unroll
                    for (int mt = 0; mt < 2; mt++) {
                        const int row = q * 32 + mt * 16 + (t >> 2);
                        #pragma unroll
                        for (int nt = 0; nt < 4; nt++) {
                            const int col = wc * 32 + nt * 8 + (t & 3) * 2;
                            int atomA = atom0 + row;
                            int atomB = atomA + 8;
                            if (atomA < N) {
                                float2* p = (float2*)(g_E + ((size_t)a * N + atomA) * DD + col);
                                *p = make_float2(D[mt][nt][0], D[mt][nt][1]);
                            }
                            if (atomB < N) {
                                float2* p = (float2*)(g_E + ((size_t)a * N + atomB) * DD + col);
                                *p = make_float2(D[mt][nt][2], D[mt][nt][3]);
                            }
                        }
                    }
                }
                __syncthreads();   // A region reuse next tile
            }
        }

        // ---- software grid barrier (all blocks resident: 1 block/SM) ----
        __syncthreads();
        if (tid == 0) {
            __threadfence();
            unsigned arrived = atomicAdd(&g_barrier, 1u) + 1u;
            if (arrived < gridDim.x) {
                while (*(volatile unsigned int*)&g_barrier < gridDim.x) { }
            }
            __threadfence();
        }
        __syncthreads();
    }

    // ================== PHASE P: propers ==================
    // load W1/W2 images into W_SM
    {
        const float4* src = (const float4*)g_Bimg;
        float4* dst = (float4*)(smem_raw + W_SM);
        for (int i = tid; i < 4 * IMG_BYTES / 16; i += 512) dst[i] = src[i];
    }
    __syncthreads();

    // named barrier for this quarter (ids 1..4), 128 threads each
    #define QBAR() asm volatile("bar.sync %0, %1;" :: "r"(q + 1), "r"(128) : "memory")

    // deterministic stagger: anti-phase the 4 quarters' MMA bursts
    if (q) __nanosleep(3000u * (uint32_t)q);

    const uint32_t aBase = sb + (uint32_t)(q * 2 * A_SIZE_Q);
    const uint32_t aHi0 = aBase + lane_off;                       // rows 0..15
    const uint32_t aHi1 = aBase + 16u * PITCH_B + lane_off;       // rows 16..31
    const uint32_t aLo0 = aHi0 + A_SIZE_Q;
    const uint32_t aLo1 = aHi1 + A_SIZE_Q;

    const uint32_t bW = sb + W_SM + (uint32_t)(wc * 32) * PITCH_B + lane_off;
    const uint32_t b1Hi0 = bW;
    const uint32_t b1Hi1 = bW + 16u * PITCH_B;
    const uint32_t b1Lo0 = b1Hi0 + IMG_BYTES;
    const uint32_t b1Lo1 = b1Hi1 + IMG_BYTES;
    const uint32_t b2Hi0 = b1Hi0 + 2 * IMG_BYTES;
    const uint32_t b2Hi1 = b1Hi1 + 2 * IMG_BYTES;
    const uint32_t b2Lo0 = b1Lo0 + 2 * IMG_BYTES;
    const uint32_t b2Lo1 = b1Lo1 + 2 * IMG_BYTES;

    char* const Araw = smem_raw + q * 2 * A_SIZE_Q;

    const int n_qt    = (P + 7) >> 3;             // 8-proper quarter-tiles
    const int stream  = blockIdx.x * 4 + q;
    const int stride  = gridDim.x * 4;

    const int lp = tid_q >> 4;        // proper within tile (0..7)
    const int u  = tid_q & 15;        // 8-col chunk

    int parity = 0;

    for (int qt = stream; qt < n_qt; qt += stride, parity ^= 1) {
        const int pbase = qt * 8;

        float* qm    = qmbase + parity * 256;
        float* ssin  = qm;                // 32
        float* scos  = qm + 32;
        float* sdl   = qm + 64;
        float* sdh   = qm + 96;           // 96
        float* sdelta= qm + 192;          // 64

        // ---- prologue: direct index loads + early E prefetch (registers) ----
        int pidx[4];
        load_prop_idx(propers_raw, is64, pbase + lp, P, N, pidx);
        const float* E0 = g_E + (size_t)pidx[0] * DD + u * 8;
        const float* E1 = g_E + ((size_t)N * 1 + pidx[1]) * DD + u * 8;
        const float* E2 = g_E + ((size_t)N * 2 + pidx[2]) * DD + u * 8;
        const float* E3 = g_E + ((size_t)N * 3 + pidx[3]) * DD + u * 8;
        float4 e0a = *(const float4*)(E0);
        float4 e0b = *(const float4*)(E0 + 4);
        float4 e1a = *(const float4*)(E1);
        float4 e1b = *(const float4*)(E1 + 4);
        float4 e2a = *(const float4*)(E2);
        float4 e2b = *(const float4*)(E2 + 4);
        float4 e3a = *(const float4*)(E3);
        float4 e3b = *(const float4*)(E3 + 4);

        // ---- geometry (32 threads), sdelta zero (64 threads) ----
        if (tid_q < 32) {
            const int row = tid_q;
            const int glp = row >> 2;
            const int tt  = row & 3;
            int gidx[4];
            load_prop_idx(propers_raw, is64, pbase + glp, P, N, gidx);

            const float* c0 = coords + (size_t)(gidx[0] * TT + tt) * 3;
            const float* c1 = coords + (size_t)(gidx[1] * TT + tt) * 3;
            const float* c2 = coords + (size_t)(gidx[2] * TT + tt) * 3;
            const float* c3 = coords + (size_t)(gidx[3] * TT + tt) * 3;

            float c0x = c0[0], c0y = c0[1], c0z = c0[2];
            float c1x = c1[0], c1y = c1[1], c1z = c1[2];
            float c2x = c2[0], c2y = c2[1], c2z = c2[2];
            float c3x = c3[0], c3y = c3[1], c3z = c3[2];

            float u1x = c1x - c0x, u1y = c1y - c0y, u1z = c1z - c0z;
            float u2x = c2x - c1x, u2y = c2y - c1y, u2z = c2z - c1z;
            float u3x = c3x - c2x, u3y = c3y - c2y, u3z = c3z - c2z;

            float ax = u1y * u2z - u1z * u2y;
            float ay = u1z * u2x - u1x * u2z;
            float az = u1x * u2y - u1y * u2x;
            float bx = u2y * u3z - u2z * u3y;
            float by = u2z * u3x - u2x * u3z;
            float bz = u2x * u3y - u2y * u3x;

            float x   = ax * bx + ay * by + az * bz;
            float u2n = sqrtf(u2x * u2x + u2y * u2y + u2z * u2z);
            float y   = u2n * (u1x * bx + u1y * by + u1z * bz);

            float r2 = x * x + y * y;
            float s, c;
            if (r2 > 1e-30f) {
                float rinv = rsqrtf(r2);
                s = y * rinv;
                c = x * rinv;
            } else { s = 0.f; c = 1.f; }

            float drx = c0x - c3x, dry = c0y - c3y, drz = c0z - c3z;
            float dl  = sqrtf(fmaxf(drx * drx + dry * dry + drz * drz, 1e-12f));
            float inv = 1.f / dl;

            ssin[row] = s;
            scos[row] = c;
            sdl[row]  = dl;
            sdh[row * 3 + 0] = drx * inv;
            sdh[row * 3 + 1] = dry * inv;
            sdh[row * 3 + 2] = drz * inv;
        } else if (tid_q < 96) {
            sdelta[tid_q - 32] = 0.f;
        }
        QBAR();

        // ---- layer 0: E register sums + scalar feats -> split bf16 A tile ----
        {
            const int col0 = u * 8;
            float4 bbA = *(const float4*)(vb0 + col0);
            float4 bbB = *(const float4*)(vb0 + col0 + 4);
            float sAx = e0a.x + e1a.x + e2a.x + e3a.x + bbA.x;
            float sAy = e0a.y + e1a.y + e2a.y + e3a.y + bbA.y;
            float sAz = e0a.z + e1a.z + e2a.z + e3a.z + bbA.z;
            float sAw = e0a.w + e1a.w + e2a.w + e3a.w + bbA.w;
            float sBx = e0b.x + e1b.x + e2b.x + e3b.x + bbB.x;
            float sBy = e0b.y + e1b.y + e2b.y + e3b.y + bbB.y;
            float sBz = e0b.z + e1b.z + e2b.z + e3b.z + bbB.z;
            float sBw = e0b.w + e1b.w + e2b.w + e3b.w + bbB.w;
            float4 vtA = *(const float4*)(vwt + col0);
            float4 vtB = *(const float4*)(vwt + col0 + 4);
            float4 vsA = *(const float4*)(vws + col0);
            float4 vsB = *(const float4*)(vws + col0 + 4);
            float4 vcA = *(const float4*)(vwc + col0);
            float4 vcB = *(const float4*)(vwc + col0 + 4);
            float4 vdA = *(const float4*)(vwd + col0);
            float4 vdB = *(const float4*)(vwd + col0 + 4);

            #pragma unroll
            for (int tt = 0; tt < TT; tt++) {
                const int row = lp * 4 + tt;
                float tv = stv[tt];
                float sv = ssin[row];
                float cv = scos[row];
                float dv = sdl[row];
                float vA0 = sAx + tv * vtA.x + sv * vsA.x + cv * vcA.x + dv * vdA.x;
                float vA1 = sAy + tv * vtA.y + sv * vsA.y + cv * vcA.y + dv * vdA.y;
                float vA2 = sAz + tv * vtA.z + sv * vsA.z + cv * vcA.z + dv * vdA.z;
                float vA3 = sAw + tv * vtA.w + sv * vsA.w + cv * vcA.w + dv * vdA.w;
                float vB0 = sBx + tv * vtB.x + sv * vsB.x + cv * vcB.x + dv * vdB.x;
                float vB1 = sBy + tv * vtB.y + sv * vsB.y + cv * vcB.y + dv * vdB.y;
                float vB2 = sBz + tv * vtB.z + sv * vsB.z + cv * vcB.z + dv * vdB.z;
                float vB3 = sBw + tv * vtB.w + sv * vsB.w + cv * vcB.w + dv * vdB.w;
                vA0 = (vA0 > 0.f) ? vA0 : 0.001f * vA0;
                vA1 = (vA1 > 0.f) ? vA1 : 0.001f * vA1;
                vA2 = (vA2 > 0.f) ? vA2 : 0.001f * vA2;
                vA3 = (vA3 > 0.f) ? vA3 : 0.001f * vA3;
                vB0 = (vB0 > 0.f) ? vB0 : 0.001f * vB0;
                vB1 = (vB1 > 0.f) ? vB1 : 0.001f * vB1;
                vB2 = (vB2 > 0.f) ? vB2 : 0.001f * vB2;
                vB3 = (vB3 > 0.f) ? vB3 : 0.001f * vB3;
                uint4 hiv, lov;
                hiv.x = pack_split(vA0, vA1, lov.x);
                hiv.y = pack_split(vA2, vA3, lov.y);
                hiv.z = pack_split(vB0, vB1, lov.z);
                hiv.w = pack_split(vB2, vB3, lov.w);
                uint32_t o = (uint32_t)row * PITCH_B + (uint32_t)col0 * 2;
                *(uint4*)(Araw + o)            = hiv;
                *(uint4*)(Araw + A_SIZE_Q + o) = lov;
            }
        }
        QBAR();

        // ================= layer 1 =================
        float D[2][4][4];
        gemm_layer(D, aHi0, aHi1, aLo0, aLo1, b1Hi0, b1Hi1, b1Lo0, b1Lo1);

        QBAR();

        // ---- epilogue 1: bias + leaky, re-split into A tile ----
        {
            #pragma unroll
            for (int mt = 0; mt < 2; mt++) {
                const int r0 = mt * 16 + (t >> 2);
                #pragma unroll
                for (int nt = 0; nt < 4; nt++) {
                    const int c = wc * 32 + nt * 8 + (t & 3) * 2;
                    float bia = vb1[c], bib = vb1[c + 1];
                    float v0 = D[mt][nt][0] + bia, v1 = D[mt][nt][1] + bib;
                    float v2 = D[mt][nt][2] + bia, v3 = D[mt][nt][3] + bib;
                    v0 = (v0 > 0.f) ? v0 : 0.001f * v0;
                    v1 = (v1 > 0.f) ? v1 : 0.001f * v1;
                    v2 = (v2 > 0.f) ? v2 : 0.001f * v2;
                    v3 = (v3 > 0.f) ? v3 : 0.001f * v3;
                    uint32_t lo0, hi0 = pack_split(v0, v1, lo0);
                    uint32_t lo1, hi1 = pack_split(v2, v3, lo1);
                    uint32_t oA = (uint32_t)r0 * PITCH_B + (uint32_t)c * 2;
                    uint32_t oB = oA + 8u * PITCH_B;
                    *(uint32_t*)(Araw + oA)            = hi0;
                    *(uint32_t*)(Araw + A_SIZE_Q + oA) = lo0;
                    *(uint32_t*)(Araw + oB)            = hi1;
                    *(uint32_t*)(Araw + A_SIZE_Q + oB) = lo1;
                }
            }
        }
        QBAR();

        // ================= layer 2 =================
        gemm_layer(D, aHi0, aHi1, aLo0, aLo1, b2Hi0, b2Hi1, b2Lo0, b2Lo1);

        // ---- epilogue 2: bias+leaky, partial delta over this warp's 32 cols ----
        {
            float a0[2][2], a1[2][2];
            #pragma unroll
            for (int mt = 0; mt < 2; mt++)
                a0[mt][0] = a0[mt][1] = a1[mt][0] = a1[mt][1] = 0.f;

            #pragma unroll
            for (int mt = 0; mt < 2; mt++) {
                #pragma unroll
                for (int nt = 0; nt < 4; nt++) {
                    const int c = wc * 32 + nt * 8 + (t & 3) * 2;
                    float bia = vb2[c], bib = vb2[c + 1];
                    float v0 = D[mt][nt][0] + bia, v1 = D[mt][nt][1] + bib;
                    float v2 = D[mt][nt][2] + bia, v3 = D[mt][nt][3] + bib;
                    v0 = (v0 > 0.f) ? v0 : 0.001f * v0;
                    v1 = (v1 > 0.f) ? v1 : 0.001f * v1;
                    v2 = (v2 > 0.f) ? v2 : 0.001f * v2;
                    v3 = (v3 > 0.f) ? v3 : 0.001f * v3;
                    float w00 = sW3[c * 2 + 0], w01 = sW3[c * 2 + 1];
                    float w10 = sW3[c * 2 + 2], w11 = sW3[c * 2 + 3];
                    a0[mt][0] += v0 * w00 + v1 * w10;
                    a1[mt][0] += v0 * w01 + v1 * w11;
                    a0[mt][1] += v2 * w00 + v3 * w10;
                    a1[mt][1] += v2 * w01 + v3 * w11;
                }
            }
            #pragma unroll
            for (int off = 1; off <= 2; off <<= 1) {
                #pragma unroll
                for (int mt = 0; mt < 2; mt++) {
                    a0[mt][0] += __shfl_xor_sync(0xffffffffu, a0[mt][0], off);
                    a1[mt][0] += __shfl_xor_sync(0xffffffffu, a1[mt][0], off);
                    a0[mt][1] += __shfl_xor_sync(0xffffffffu, a0[mt][1], off);
                    a1[mt][1] += __shfl_xor_sync(0xffffffffu, a1[mt][1], off);
                }
            }
            if ((t & 3) == 0) {
                #pragma unroll
                for (int mt = 0; mt < 2; mt++) {
                    #pragma unroll
                    for (int half = 0; half < 2; half++) {
                        const int row = mt * 16 + (t >> 2) + half * 8;
                        atomicAdd(&sdelta[row * 2 + 0], a0[mt][half]);
                        atomicAdd(&sdelta[row * 2 + 1], a1[mt][half]);
                    }
                }
            }
        }
        QBAR();

        // ---- scatter; no trailing barrier (parity double-buffered misc) ----
        if (tid_q < 32) {
            const int row = tid_q;
            const int glp = row >> 2;
            const int tt  = row & 3;
            const int p   = pbase + glp;
            if (p < P) {
                int gidx[4];
                load_prop_idx(propers_raw, is64, p, P, N, gidx);
                const float d0 = sdelta[row * 2 + 0] + vb3[0];
                const float d1 = sdelta[row * 2 + 1] + vb3[1];
                float hx = sdh[row * 3 + 0];
                float hy = sdh[row * 3 + 1];
                float hz = sdh[row * 3 + 2];
                float* o0 = out + (size_t)(gidx[0] * TT + tt) * 3;
                float* o3 = out + (size_t)(gidx[3] * TT + tt) * 3;
                atomicAdd(o0 + 0, -0.5f * d0 * hx);
                atomicAdd(o0 + 1, -0.5f * d0 * hy);
                atomicAdd(o0 + 2, -0.5f * d0 * hz);
                atomicAdd(o3 + 0,  0.5f * d1 * hx);
                atomicAdd(o3 + 1,  0.5f * d1 * hy);
                atomicAdd(o3 + 2,  0.5f * d1 * hz);
            }
        }
    }
    #undef QBAR
}

// ---------------------------------------------------------------------------
extern "C" void kernel_launch(void* const* d_in, const int* in_sizes, int n_in,
                              void* d_out, int out_size)
{
    const float* coords  = (const float*)d_in[0];
    const void*  propers = d_in[1];
    const float* enc     = (const float*)d_in[2];
    const float* t_arr   = (const float*)d_in[3];
    const float* answer  = (const float*)d_in[4];
    const float* W0      = (const float*)d_in[5];
    const float* b0      = (const float*)d_in[6];
    const float* W1      = (const float*)d_in[7];
    const float* b1      = (const float*)d_in[8];
    const float* W2      = (const float*)d_in[9];
    const float* b2      = (const float*)d_in[10];
    const float* W3      = (const float*)d_in[11];
    const float* b3      = (const float*)d_in[12];
    float*       out     = (float*)d_out;

    const int N = in_sizes[2] / DD;
    const int P = in_sizes[1] / 4;

    int dev = 0, sms = 148;
    cudaGetDevice(&dev);
    cudaDeviceGetAttribute(&sms, cudaDevAttrMultiProcessorCount, dev);

    int nwords = in_sizes[1] < 4096 ? in_sizes[1] : 4096;
    prep_all_kernel<<<193, 256>>>((const int*)propers, nwords, W0, W1, W2);

    cudaMemcpyAsync(out, answer, sizeof(float) * (size_t)in_sizes[4],
                    cudaMemcpyDeviceToDevice, 0);

    cudaFuncSetAttribute(fused_kernel,
                         cudaFuncAttributeMaxDynamicSharedMemorySize, SMEM_TOTAL);
    fused_kernel<<<sms, 512, SMEM_TOTAL>>>(
        coords, propers, t_arr, enc, W0, b0, b1, b2, W3, b3, out, N, P);
}

// round 16
// speedup vs baseline: 1.0924x; 1.0924x over previous
#include <cuda_runtime.h>
#include <cuda_bf16.h>
#include <cstdint>

#define DD   128
#define TT   4

// ---------------------------------------------------------------------------
// Global scratch
// ---------------------------------------------------------------------------
__device__ float g_E[4L * 25000 * DD];  // per-atom layer-0 partials (51.2 MB)
__device__ int   g_idx64;               // propers dtype flag
#define PITCH_B   272                   // 136 bf16 * 2 bytes
#define IMG_BYTES 34816                 // 128 * 272
__device__ __align__(16) unsigned char g_Bimg[4 * IMG_BYTES];    // W1hi,W1lo,W2hi,W2lo
__device__ __align__(16) unsigned char g_B0img[8 * IMG_BYTES];   // W0 chunks 0..3 (hi,lo)

// ---------------------------------------------------------------------------
// helpers
// ---------------------------------------------------------------------------
__device__ __forceinline__ uint32_t pack_split(float v0, float v1, uint32_t& lo_out) {
    __nv_bfloat162 h2 = __floats2bfloat162_rn(v0, v1);
    float r0 = v0 - __bfloat162float(h2.x);
    float r1 = v1 - __bfloat162float(h2.y);
    __nv_bfloat162 l2 = __floats2bfloat162_rn(r0, r1);
    lo_out = *reinterpret_cast<uint32_t*>(&l2);
    return *reinterpret_cast<uint32_t*>(&h2);
}

__device__ __forceinline__ void mma16816(float d[4], const uint32_t a[4],
                                         uint32_t b0, uint32_t b1) {
    asm volatile(
        "mma.sync.aligned.m16n8k16.row.col.f32.bf16.bf16.f32 "
        "{%0,%1,%2,%3}, {%4,%5,%6,%7}, {%8,%9}, {%0,%1,%2,%3};"
        : "+f"(d[0]), "+f"(d[1]), "+f"(d[2]), "+f"(d[3])
        : "r"(a[0]), "r"(a[1]), "r"(a[2]), "r"(a[3]), "r"(b0), "r"(b1));
}

__device__ __forceinline__ void ldm4(uint32_t r[4], uint32_t saddr) {
    asm volatile("ldmatrix.sync.aligned.m8n8.x4.shared.b16 {%0,%1,%2,%3}, [%4];"
        : "=r"(r[0]), "=r"(r[1]), "=r"(r[2]), "=r"(r[3]) : "r"(saddr));
}

__device__ __forceinline__ void cp_async16(uint32_t saddr, const void* gptr) {
    asm volatile("cp.async.cg.shared.global [%0], [%1], 16;"
                 :: "r"(saddr), "l"(gptr));
}
#define CP_ASYNC_WAIT_ALL() asm volatile("cp.async.wait_all;" ::: "memory")

__device__ __forceinline__ void load_prop_idx(const void* propers_raw, int is64,
                                              int p, int P, int N, int idx[4]) {
    if (p < P) {
        if (is64) {
            longlong2 a = ((const longlong2*)propers_raw)[(size_t)p * 2];
            longlong2 b = ((const longlong2*)propers_raw)[(size_t)p * 2 + 1];
            idx[0] = (int)a.x; idx[1] = (int)a.y;
            idx[2] = (int)b.x; idx[3] = (int)b.y;
        } else {
            int4 v = ((const int4*)propers_raw)[p];
            idx[0] = v.x; idx[1] = v.y; idx[2] = v.z; idx[3] = v.w;
        }
    } else {
        idx[0] = idx[1] = idx[2] = idx[3] = 0;
    }
    #pragma unroll
    for (int j = 0; j < 4; j++) {
        int v = idx[j];
        v = v < 0 ? 0 : v;
        idx[j] = v >= N ? N - 1 : v;
    }
}

// ---------------------------------------------------------------------------
// merged prep kernel
// ---------------------------------------------------------------------------
__global__ void prep_all_kernel(const int* __restrict__ prop_words, int nwords,
                                const float* __restrict__ W0,
                                const float* __restrict__ W1,
                                const float* __restrict__ W2)
{
    const int b = blockIdx.x;
    if (b == 0) {
        __shared__ int nz;
        if (threadIdx.x == 0) nz = 0;
        __syncthreads();
        for (int i = 1 + 2 * threadIdx.x; i < nwords; i += 2 * blockDim.x) {
            if (prop_words[i] != 0) { atomicOr(&nz, 1); break; }
        }
        __syncthreads();
        if (threadIdx.x == 0) g_idx64 = (nz == 0) ? 1 : 0;
    } else if (b <= 64) {
        int idx = (b - 1) * 256 + threadIdx.x;
        int l = idx >> 13;
        int r = idx & 8191;
        int n = r >> 6;
        int k = (r & 63) * 2;
        const float* W = l ? W2 : W1;
        float v0 = W[(size_t)k * DD + n];
        float v1 = W[(size_t)(k + 1) * DD + n];
        uint32_t lo, hi = pack_split(v0, v1, lo);
        uint32_t off = (uint32_t)n * PITCH_B + (uint32_t)k * 2;
        *(uint32_t*)(g_Bimg + (l * 2 + 0) * IMG_BYTES + off) = hi;
        *(uint32_t*)(g_Bimg + (l * 2 + 1) * IMG_BYTES + off) = lo;
    } else {
        int idx = (b - 65) * 256 + threadIdx.x;
        int a = idx >> 13;
        int r = idx & 8191;
        int n = r >> 6;
        int k = (r & 63) * 2;
        float v0 = W0[(size_t)(a * 128 + k) * DD + n];
        float v1 = W0[(size_t)(a * 128 + k + 1) * DD + n];
        uint32_t lo, hi = pack_split(v0, v1, lo);
        uint32_t off = (uint32_t)n * PITCH_B + (uint32_t)k * 2;
        *(uint32_t*)(g_B0img + (a * 2 + 0) * IMG_BYTES + off) = hi;
        *(uint32_t*)(g_B0img + (a * 2 + 1) * IMG_BYTES + off) = lo;
    }
}

// ---------------------------------------------------------------------------
// GEMM layer: per warp 32 rows x 32 cols, 3-term bf16 split (R13 form).
// ---------------------------------------------------------------------------
__device__ __forceinline__ void gemm_layer(
    float D[2][4][4],
    uint32_t aHi0, uint32_t aHi1, uint32_t aLo0, uint32_t aLo1,
    uint32_t bHi0, uint32_t bHi1, uint32_t bLo0, uint32_t bLo1)
{
    #pragma unroll
    for (int mt = 0; mt < 2; mt++)
        #pragma unroll
        for (int nt = 0; nt < 4; nt++)
            #pragma unroll
            for (int j = 0; j < 4; j++) D[mt][nt][j] = 0.f;

    #pragma unroll
    for (int ks = 0; ks < 8; ks++) {
        const uint32_t kb = ks * 32;
        uint32_t ah[2][4], al[2][4];
        ldm4(ah[0], aHi0 + kb);
        ldm4(ah[1], aHi1 + kb);
        ldm4(al[0], aLo0 + kb);
        ldm4(al[1], aLo1 + kb);
        #pragma unroll
        for (int ntp = 0; ntp < 2; ntp++) {
            uint32_t bh[4], bl[4];
            ldm4(bh, (ntp ? bHi1 : bHi0) + kb);
            ldm4(bl, (ntp ? bLo1 : bLo0) + kb);
            #pragma unroll
            for (int mt = 0; mt < 2; mt++) {
                #pragma unroll
                for (int sub = 0; sub < 2; sub++) {
                    float* d = D[mt][ntp * 2 + sub];
                    mma16816(d, ah[mt], bh[sub], bh[2 + sub]);
                    mma16816(d, ah[mt], bl[sub], bl[2 + sub]);
                    mma16816(d, al[mt], bh[sub], bh[2 + sub]);
                }
            }
        }
    }
}

// ---------------------------------------------------------------------------
// Kernel A (tensor-core): E[a][atom][j] via bf16-split MMA.
// one block = 64 atoms x ONE chunk; grid=(ceil(N/64), 4), 2/SM.
// B-image copy via cp.async, overlapped with the enc load+pack.
// ---------------------------------------------------------------------------
#define EA_SIZE 17408
#define E_A_HI  0
#define E_A_LO  EA_SIZE
#define E_B_HI  (2 * EA_SIZE)
#define E_SMEM  (2 * EA_SIZE + 2 * IMG_BYTES)   // 104448

__global__ void __launch_bounds__(256, 2) precompute_E_mma_kernel(
    const float* __restrict__ enc,
    int N)
{
    extern __shared__ char sm[];
    const int tid = threadIdx.x;
    const int w   = tid >> 5;
    const int t   = tid & 31;
    const int wr  = w >> 2;
    const int wc  = w & 3;
    const int a     = blockIdx.y;
    const int atom0 = blockIdx.x * 64;

    const uint32_t sb = (uint32_t)__cvta_generic_to_shared(sm);

    // async B-image copy (hi+lo, 69632 B) -- overlaps with enc pack below
    {
        const char* src = (const char*)(g_B0img + (size_t)(a * 2) * IMG_BYTES);
        #pragma unroll
        for (int i = tid; i < 2 * IMG_BYTES / 16; i += 256)
            cp_async16(sb + E_B_HI + (uint32_t)i * 16, src + (size_t)i * 16);
    }
    // load + split enc tile: 64 rows x 128 cols (runs while cp.async streams B)
    #pragma unroll
    for (int it = 0; it < 8; it++) {
        int idx = tid + it * 256;
        int row = idx >> 5;
        int col = (idx & 31) * 4;
        int atom = atom0 + row;
        float4 v = make_float4(0.f, 0.f, 0.f, 0.f);
        if (atom < N) v = *(const float4*)(enc + (size_t)atom * DD + col);
        uint32_t lo0, hi0 = pack_split(v.x, v.y, lo0);
        uint32_t lo1, hi1 = pack_split(v.z, v.w, lo1);
        uint32_t o = (uint32_t)row * PITCH_B + (uint32_t)col * 2;
        *(uint32_t*)(sm + E_A_HI + o)     = hi0;
        *(uint32_t*)(sm + E_A_HI + o + 4) = hi1;
        *(uint32_t*)(sm + E_A_LO + o)     = lo0;
        *(uint32_t*)(sm + E_A_LO + o + 4) = lo1;
    }
    CP_ASYNC_WAIT_ALL();
    __syncthreads();

    const int lseg = t >> 3;
    const uint32_t lane_off = (uint32_t)((t & 7) + (lseg & 1) * 8) * PITCH_B
                            + (uint32_t)(lseg >> 1) * 16;

    const uint32_t aHi0 = sb + E_A_HI + (uint32_t)(wr * 32 +  0) * PITCH_B + lane_off;
    const uint32_t aHi1 = sb + E_A_HI + (uint32_t)(wr * 32 + 16) * PITCH_B + lane_off;
    const uint32_t aLo0 = aHi0 + EA_SIZE;
    const uint32_t aLo1 = aHi1 + EA_SIZE;
    const uint32_t bHi0 = sb + E_B_HI + (uint32_t)(wc * 32 +  0) * PITCH_B + lane_off;
    const uint32_t bHi1 = sb + E_B_HI + (uint32_t)(wc * 32 + 16) * PITCH_B + lane_off;
    const uint32_t bLo0 = bHi0 + IMG_BYTES;
    const uint32_t bLo1 = bHi1 + IMG_BYTES;

    float D[2][4][4];
    gemm_layer(D, aHi0, aHi1, aLo0, aLo1, bHi0, bHi1, bLo0, bLo1);

    #pragma unroll
    for (int mt = 0; mt < 2; mt++) {
        const int row = wr * 32 + mt * 16 + (t >> 2);
        #pragma unroll
        for (int nt = 0; nt < 4; nt++) {
            const int col = wc * 32 + nt * 8 + (t & 3) * 2;
            int atomA = atom0 + row;
            int atomB = atomA + 8;
            if (atomA < N) {
                float2* p = (float2*)(g_E + ((size_t)a * N + atomA) * DD + col);
                *p = make_float2(D[mt][nt][0], D[mt][nt][1]);
            }
            if (atomB < N) {
                float2* p = (float2*)(g_E + ((size_t)a * N + atomB) * DD + col);
                *p = make_float2(D[mt][nt][2], D[mt][nt][3]);
            }
        }
    }
}

// ---------------------------------------------------------------------------
// Main fused kernel (PERSISTENT): 512 threads = FOUR independent 4-warp
// quarters, deterministically staggered to anti-phase their MMA bursts.
// Per-quarter misc is parity double-buffered -> 5 barriers/tile.
// ---------------------------------------------------------------------------
#define A_SIZE_Q 8704                      // 32 * 272 (one term, one quarter)
#define W_SM     (8 * A_SIZE_Q)            // 69632 (4 quarters x hi/lo)
#define MISC_OFF (W_SM + 4 * IMG_BYTES)    // 208896
#define MISC_FLOATS 3260
#define SMEM_TOTAL (MISC_OFF + MISC_FLOATS * 4)   // 221936

__global__ void __launch_bounds__(512, 1) propers_kernel(
    const float* __restrict__ coords,
    const void* __restrict__ propers_raw,
    const float* __restrict__ t_arr,
    const float* __restrict__ W0,
    const float* __restrict__ b0,
    const float* __restrict__ b1,
    const float* __restrict__ b2,
    const float* __restrict__ W3,
    const float* __restrict__ b3,
    float* __restrict__ out,
    int N, int P)
{
    extern __shared__ char smem_raw[];

    float* m    = (float*)(smem_raw + MISC_OFF);
    float* vb1  = m;                // 128
    float* vb2  = m + 128;          // 128
    float* vwt  = m + 256;          // 128
    float* vws  = m + 384;
    float* vwc  = m + 512;
    float* vwd  = m + 640;
    float* vb0  = m + 768;
    float* sW3  = m + 896;          // 256
    float* vb3  = m + 1152;         // 2 (+2 pad)
    float* stv  = m + 1156;         // 4

    const int tid  = threadIdx.x;
    const int w    = tid >> 5;
    const int t    = tid & 31;
    const int q    = w >> 2;          // quarter 0..3
    const int wc   = w & 3;           // col group (0..3)
    const int tid_q = tid & 127;
    const int is64 = g_idx64;

    // per-quarter misc, parity double-buffered (256 floats per parity)
    float* qmbase = m + 1160 + q * 512;

    const uint32_t sb = (uint32_t)__cvta_generic_to_shared(smem_raw);

    // ---- one-time setup (all 512 threads); W-image copy via cp.async ----
    {
        const char* src = (const char*)g_Bimg;
        for (int i = tid; i < 4 * IMG_BYTES / 16; i += 512)
            cp_async16(sb + W_SM + (uint32_t)i * 16, src + (size_t)i * 16);
    }
    if (tid < 128) {
        vwt[tid] = W0[(size_t)512 * DD + tid];
        vws[tid] = W0[(size_t)513 * DD + tid];
        vwc[tid] = W0[(size_t)514 * DD + tid];
        vwd[tid] = W0[(size_t)515 * DD + tid];
        vb0[tid] = b0[tid];
        vb1[tid] = b1[tid];
        vb2[tid] = b2[tid];
    } else if (tid < 256) {
        int i = tid - 128;
        if (i < 2)  vb3[i] = b3[i];
        if (i < TT) stv[i] = t_arr[i];
    } else if (tid < 512) {
        int i = tid - 256;
        if (i < 256) sW3[i] = W3[i];
    }
    CP_ASYNC_WAIT_ALL();
    __syncthreads();

    // named barrier for this quarter (ids 1..4), 128 threads each
    #define QBAR() asm volatile("bar.sync %0, %1;" :: "r"(q + 1), "r"(128) : "memory")

    // ---- deterministic stagger: anti-phase the 4 quarters' MMA bursts ----
    if (q) __nanosleep(3000u * (uint32_t)q);

    // ---- ldmatrix lane addressing ----
    const int lseg = t >> 3;
    const uint32_t lane_off = (uint32_t)((t & 7) + (lseg & 1) * 8) * PITCH_B
                            + (uint32_t)(lseg >> 1) * 16;

    const uint32_t aBase = sb + (uint32_t)(q * 2 * A_SIZE_Q);
    const uint32_t aHi0 = aBase + lane_off;                       // rows 0..15
    const uint32_t aHi1 = aBase + 16u * PITCH_B + lane_off;       // rows 16..31
    const uint32_t aLo0 = aHi0 + A_SIZE_Q;
    const uint32_t aLo1 = aHi1 + A_SIZE_Q;

    const uint32_t bW = sb + W_SM + (uint32_t)(wc * 32) * PITCH_B + lane_off;
    const uint32_t b1Hi0 = bW;
    const uint32_t b1Hi1 = bW + 16u * PITCH_B;
    const uint32_t b1Lo0 = b1Hi0 + IMG_BYTES;
    const uint32_t b1Lo1 = b1Hi1 + IMG_BYTES;
    const uint32_t b2Hi0 = b1Hi0 + 2 * IMG_BYTES;
    const uint32_t b2Hi1 = b1Hi1 + 2 * IMG_BYTES;
    const uint32_t b2Lo0 = b1Lo0 + 2 * IMG_BYTES;
    const uint32_t b2Lo1 = b1Lo1 + 2 * IMG_BYTES;

    char* const Araw = smem_raw + q * 2 * A_SIZE_Q;

    const int n_qt    = (P + 7) >> 3;             // 8-proper quarter-tiles
    const int stream  = blockIdx.x * 4 + q;
    const int stride  = gridDim.x * 4;

    // per-thread pack assignment (fixed across tiles)
    const int lp = tid_q >> 4;        // proper within tile (0..7)
    const int u  = tid_q & 15;        // 8-col chunk (cols u*8 .. u*8+7)

    int parity = 0;

    for (int qt = stream; qt < n_qt; qt += stride, parity ^= 1) {
        const int pbase = qt * 8;

        float* qm    = qmbase + parity * 256;
        float* ssin  = qm;                // 32
        float* scos  = qm + 32;
        float* sdl   = qm + 64;
        float* sdh   = qm + 96;           // 96
        float* sdelta= qm + 192;          // 64

        // ---- prologue: direct index loads + early E prefetch (registers) ----
        int pidx[4];
        load_prop_idx(propers_raw, is64, pbase + lp, P, N, pidx);
        const float* E0 = g_E + (size_t)pidx[0] * DD + u * 8;
        const float* E1 = g_E + ((size_t)N * 1 + pidx[1]) * DD + u * 8;
        const float* E2 = g_E + ((size_t)N * 2 + pidx[2]) * DD + u * 8;
        const float* E3 = g_E + ((size_t)N * 3 + pidx[3]) * DD + u * 8;
        float4 e0a = *(const float4*)(E0);
        float4 e0b = *(const float4*)(E0 + 4);
        float4 e1a = *(const float4*)(E1);
        float4 e1b = *(const float4*)(E1 + 4);
        float4 e2a = *(const float4*)(E2);
        float4 e2b = *(const float4*)(E2 + 4);
        float4 e3a = *(const float4*)(E3);
        float4 e3b = *(const float4*)(E3 + 4);

        // ---- geometry (32 threads), sdelta zero (64 threads) ----
        if (tid_q < 32) {
            const int row = tid_q;
            const int glp = row >> 2;
            const int tt  = row & 3;
            int gidx[4];
            load_prop_idx(propers_raw, is64, pbase + glp, P, N, gidx);

            const float* c0 = coords + (size_t)(gidx[0] * TT + tt) * 3;
            const float* c1 = coords + (size_t)(gidx[1] * TT + tt) * 3;
            const float* c2 = coords + (size_t)(gidx[2] * TT + tt) * 3;
            const float* c3 = coords + (size_t)(gidx[3] * TT + tt) * 3;

            float c0x = c0[0], c0y = c0[1], c0z = c0[2];
            float c1x = c1[0], c1y = c1[1], c1z = c1[2];
            float c2x = c2[0], c2y = c2[1], c2z = c2[2];
            float c3x = c3[0], c3y = c3[1], c3z = c3[2];

            float u1x = c1x - c0x, u1y = c1y - c0y, u1z = c1z - c0z;
            float u2x = c2x - c1x, u2y = c2y - c1y, u2z = c2z - c1z;
            float u3x = c3x - c2x, u3y = c3y - c2y, u3z = c3z - c2z;

            float ax = u1y * u2z - u1z * u2y;
            float ay = u1z * u2x - u1x * u2z;
            float az = u1x * u2y - u1y * u2x;
            float bx = u2y * u3z - u2z * u3y;
            float by = u2z * u3x - u2x * u3z;
            float bz = u2x * u3y - u2y * u3x;

            float x   = ax * bx + ay * by + az * bz;
            float u2n = sqrtf(u2x * u2x + u2y * u2y + u2z * u2z);
            float y   = u2n * (u1x * bx + u1y * by + u1z * bz);

            float r2 = x * x + y * y;
            float s, c;
            if (r2 > 1e-30f) {
                float rinv = rsqrtf(r2);
                s = y * rinv;
                c = x * rinv;
            } else { s = 0.f; c = 1.f; }

            float drx = c0x - c3x, dry = c0y - c3y, drz = c0z - c3z;
            float dl  = sqrtf(fmaxf(drx * drx + dry * dry + drz * drz, 1e-12f));
            float inv = 1.f / dl;

            ssin[row] = s;
            scos[row] = c;
            sdl[row]  = dl;
            sdh[row * 3 + 0] = drx * inv;
            sdh[row * 3 + 1] = dry * inv;
            sdh[row * 3 + 2] = drz * inv;
        } else if (tid_q < 96) {
            sdelta[tid_q - 32] = 0.f;
        }
        QBAR();

        // ---- layer 0: E register sums + scalar feats -> split bf16 A tile ----
        {
            const int col0 = u * 8;
            float4 bbA = *(const float4*)(vb0 + col0);
            float4 bbB = *(const float4*)(vb0 + col0 + 4);
            float sAx = e0a.x + e1a.x + e2a.x + e3a.x + bbA.x;
            float sAy = e0a.y + e1a.y + e2a.y + e3a.y + bbA.y;
            float sAz = e0a.z + e1a.z + e2a.z + e3a.z + bbA.z;
            float sAw = e0a.w + e1a.w + e2a.w + e3a.w + bbA.w;
            float sBx = e0b.x + e1b.x + e2b.x + e3b.x + bbB.x;
            float sBy = e0b.y + e1b.y + e2b.y + e3b.y + bbB.y;
            float sBz = e0b.z + e1b.z + e2b.z + e3b.z + bbB.z;
            float sBw = e0b.w + e1b.w + e2b.w + e3b.w + bbB.w;
            float4 vtA = *(const float4*)(vwt + col0);
            float4 vtB = *(const float4*)(vwt + col0 + 4);
            float4 vsA = *(const float4*)(vws + col0);
            float4 vsB = *(const float4*)(vws + col0 + 4);
            float4 vcA = *(const float4*)(vwc + col0);
            float4 vcB = *(const float4*)(vwc + col0 + 4);
            float4 vdA = *(const float4*)(vwd + col0);
            float4 vdB = *(const float4*)(vwd + col0 + 4);

            #pragma unroll
            for (int tt = 0; tt < TT; tt++) {
                const int row = lp * 4 + tt;
                float tv = stv[tt];
                float sv = ssin[row];
                float cv = scos[row];
                float dv = sdl[row];
                float vA0 = sAx + tv * vtA.x + sv * vsA.x + cv * vcA.x + dv * vdA.x;
                float vA1 = sAy + tv * vtA.y + sv * vsA.y + cv * vcA.y + dv * vdA.y;
                float vA2 = sAz + tv * vtA.z + sv * vsA.z + cv * vcA.z + dv * vdA.z;
                float vA3 = sAw + tv * vtA.w + sv * vsA.w + cv * vcA.w + dv * vdA.w;
                float vB0 = sBx + tv * vtB.x + sv * vsB.x + cv * vcB.x + dv * vdB.x;
                float vB1 = sBy + tv * vtB.y + sv * vsB.y + cv * vcB.y + dv * vdB.y;
                float vB2 = sBz + tv * vtB.z + sv * vsB.z + cv * vcB.z + dv * vdB.z;
                float vB3 = sBw + tv * vtB.w + sv * vsB.w + cv * vcB.w + dv * vdB.w;
                vA0 = (vA0 > 0.f) ? vA0 : 0.001f * vA0;
                vA1 = (vA1 > 0.f) ? vA1 : 0.001f * vA1;
                vA2 = (vA2 > 0.f) ? vA2 : 0.001f * vA2;
                vA3 = (vA3 > 0.f) ? vA3 : 0.001f * vA3;
                vB0 = (vB0 > 0.f) ? vB0 : 0.001f * vB0;
                vB1 = (vB1 > 0.f) ? vB1 : 0.001f * vB1;
                vB2 = (vB2 > 0.f) ? vB2 : 0.001f * vB2;
                vB3 = (vB3 > 0.f) ? vB3 : 0.001f * vB3;
                uint4 hiv, lov;
                hiv.x = pack_split(vA0, vA1, lov.x);
                hiv.y = pack_split(vA2, vA3, lov.y);
                hiv.z = pack_split(vB0, vB1, lov.z);
                hiv.w = pack_split(vB2, vB3, lov.w);
                uint32_t o = (uint32_t)row * PITCH_B + (uint32_t)col0 * 2;
                *(uint4*)(Araw + o)            = hiv;
                *(uint4*)(Araw + A_SIZE_Q + o) = lov;
            }
        }
        QBAR();

        // ================= layer 1 =================
        float D[2][4][4];
        gemm_layer(D, aHi0, aHi1, aLo0, aLo1, b1Hi0, b1Hi1, b1Lo0, b1Lo1);

        QBAR();   // all quarter-warps done reading A before overwrite

        // ---- epilogue 1: bias + leaky, re-split into A tile ----
        {
            #pragma unroll
            for (int mt = 0; mt < 2; mt++) {
                const int r0 = mt * 16 + (t >> 2);
                #pragma unroll
                for (int nt = 0; nt < 4; nt++) {
                    const int c = wc * 32 + nt * 8 + (t & 3) * 2;
                    float bia = vb1[c], bib = vb1[c + 1];
                    float v0 = D[mt][nt][0] + bia, v1 = D[mt][nt][1] + bib;
                    float v2 = D[mt][nt][2] + bia, v3 = D[mt][nt][3] + bib;
                    v0 = (v0 > 0.f) ? v0 : 0.001f * v0;
                    v1 = (v1 > 0.f) ? v1 : 0.001f * v1;
                    v2 = (v2 > 0.f) ? v2 : 0.001f * v2;
                    v3 = (v3 > 0.f) ? v3 : 0.001f * v3;
                    uint32_t lo0, hi0 = pack_split(v0, v1, lo0);
                    uint32_t lo1, hi1 = pack_split(v2, v3, lo1);
                    uint32_t oA = (uint32_t)r0 * PITCH_B + (uint32_t)c * 2;
                    uint32_t oB = oA + 8u * PITCH_B;
                    *(uint32_t*)(Araw + oA)            = hi0;
                    *(uint32_t*)(Araw + A_SIZE_Q + oA) = lo0;
                    *(uint32_t*)(Araw + oB)            = hi1;
                    *(uint32_t*)(Araw + A_SIZE_Q + oB) = lo1;
                }
            }
        }
        QBAR();

        // ================= layer 2 =================
        gemm_layer(D, aHi0, aHi1, aLo0, aLo1, b2Hi0, b2Hi1, b2Lo0, b2Lo1);

        // ---- epilogue 2: bias+leaky, partial delta over this warp's 32 cols ----
        {
            float a0[2][2], a1[2][2];
            #pragma unroll
            for (int mt = 0; mt < 2; mt++)
                a0[mt][0] = a0[mt][1] = a1[mt][0] = a1[mt][1] = 0.f;

            #pragma unroll
            for (int mt = 0; mt < 2; mt++) {
                #pragma unroll
                for (int nt = 0; nt < 4; nt++) {
                    const int c = wc * 32 + nt * 8 + (t & 3) * 2;
                    float bia = vb2[c], bib = vb2[c + 1];
                    float v0 = D[mt][nt][0] + bia, v1 = D[mt][nt][1] + bib;
                    float v2 = D[mt][nt][2] + bia, v3 = D[mt][nt][3] + bib;
                    v0 = (v0 > 0.f) ? v0 : 0.001f * v0;
                    v1 = (v1 > 0.f) ? v1 : 0.001f * v1;
                    v2 = (v2 > 0.f) ? v2 : 0.001f * v2;
                    v3 = (v3 > 0.f) ? v3 : 0.001f * v3;
                    float w00 = sW3[c * 2 + 0], w01 = sW3[c * 2 + 1];
                    float w10 = sW3[c * 2 + 2], w11 = sW3[c * 2 + 3];
                    a0[mt][0] += v0 * w00 + v1 * w10;
                    a1[mt][0] += v0 * w01 + v1 * w11;
                    a0[mt][1] += v2 * w00 + v3 * w10;
                    a1[mt][1] += v2 * w01 + v3 * w11;
                }
            }
            #pragma unroll
            for (int off = 1; off <= 2; off <<= 1) {
                #pragma unroll
                for (int mt = 0; mt < 2; mt++) {
                    a0[mt][0] += __shfl_xor_sync(0xffffffffu, a0[mt][0], off);
                    a1[mt][0] += __shfl_xor_sync(0xffffffffu, a1[mt][0], off);
                    a0[mt][1] += __shfl_xor_sync(0xffffffffu, a0[mt][1], off);
                    a1[mt][1] += __shfl_xor_sync(0xffffffffu, a1[mt][1], off);
                }
            }
            if ((t & 3) == 0) {
                #pragma unroll
                for (int mt = 0; mt < 2; mt++) {
                    #pragma unroll
                    for (int half = 0; half < 2; half++) {
                        const int row = mt * 16 + (t >> 2) + half * 8;
                        atomicAdd(&sdelta[row * 2 + 0], a0[mt][half]);
                        atomicAdd(&sdelta[row * 2 + 1], a1[mt][half]);
                    }
                }
            }
        }
        QBAR();

        // ---- scatter (direct index reloads); NO trailing barrier (parity
        //      double-buffered misc; same-buffer reuse is 2 tiles away) ----
        if (tid_q < 32) {
            const int row = tid_q;
            const int glp = row >> 2;
            const int tt  = row & 3;
            const int p   = pbase + glp;
            if (p < P) {
                int gidx[4];
                load_prop_idx(propers_raw, is64, p, P, N, gidx);
                const float d0 = sdelta[row * 2 + 0] + vb3[0];
                const float d1 = sdelta[row * 2 + 1] + vb3[1];
                float hx = sdh[row * 3 + 0];
                float hy = sdh[row * 3 + 1];
                float hz = sdh[row * 3 + 2];
                float* o0 = out + (size_t)(gidx[0] * TT + tt) * 3;
                float* o3 = out + (size_t)(gidx[3] * TT + tt) * 3;
                atomicAdd(o0 + 0, -0.5f * d0 * hx);
                atomicAdd(o0 + 1, -0.5f * d0 * hy);
                atomicAdd(o0 + 2, -0.5f * d0 * hz);
                atomicAdd(o3 + 0,  0.5f * d1 * hx);
                atomicAdd(o3 + 1,  0.5f * d1 * hy);
                atomicAdd(o3 + 2,  0.5f * d1 * hz);
            }
        }
    }
    #undef QBAR
}

// ---------------------------------------------------------------------------
extern "C" void kernel_launch(void* const* d_in, const int* in_sizes, int n_in,
                              void* d_out, int out_size)
{
    const float* coords  = (const float*)d_in[0];
    const void*  propers = d_in[1];
    const float* enc     = (const float*)d_in[2];
    const float* t_arr   = (const float*)d_in[3];
    const float* answer  = (const float*)d_in[4];
    const float* W0      = (const float*)d_in[5];
    const float* b0      = (const float*)d_in[6];
    const float* W1      = (const float*)d_in[7];
    const float* b1      = (const float*)d_in[8];
    const float* W2      = (const float*)d_in[9];
    const float* b2      = (const float*)d_in[10];
    const float* W3      = (const float*)d_in[11];
    const float* b3      = (const float*)d_in[12];
    float*       out     = (float*)d_out;

    const int N = in_sizes[2] / DD;
    const int P = in_sizes[1] / 4;

    int dev = 0, sms = 148;
    cudaGetDevice(&dev);
    cudaDeviceGetAttribute(&sms, cudaDevAttrMultiProcessorCount, dev);

    int nwords = in_sizes[1] < 4096 ? in_sizes[1] : 4096;
    prep_all_kernel<<<193, 256>>>((const int*)propers, nwords, W0, W1, W2);

    cudaMemcpyAsync(out, answer, sizeof(float) * (size_t)in_sizes[4],
                    cudaMemcpyDeviceToDevice, 0);

    cudaFuncSetAttribute(precompute_E_mma_kernel,
                         cudaFuncAttributeMaxDynamicSharedMemorySize, E_SMEM);
    precompute_E_mma_kernel<<<dim3((N + 63) / 64, 4), 256, E_SMEM>>>(enc, N);

    cudaFuncSetAttribute(propers_kernel,
                         cudaFuncAttributeMaxDynamicSharedMemorySize, SMEM_TOTAL);
    propers_kernel<<<sms, 512, SMEM_TOTAL>>>(
        coords, propers, t_arr, W0, b0, b1, b2, W3, b3, out, N, P);
}

// round 17
// speedup vs baseline: 1.1097x; 1.0159x over previous
#include <cuda_runtime.h>
#include <cuda_bf16.h>
#include <cstdint>

#define DD   128
#define TT   4

// ---------------------------------------------------------------------------
// Global scratch
// ---------------------------------------------------------------------------
__device__ float g_E[4L * 25000 * DD];  // per-atom layer-0 partials (51.2 MB)
__device__ int   g_idx64;               // propers dtype flag
#define PITCH_B   272                   // 136 bf16 * 2 bytes
#define IMG_BYTES 34816                 // 128 * 272
__device__ __align__(16) unsigned char g_Bimg[4 * IMG_BYTES];    // W1hi,W1lo,W2hi,W2lo
__device__ __align__(16) unsigned char g_B0img[8 * IMG_BYTES];   // W0 chunks 0..3 (hi,lo)

// ---------------------------------------------------------------------------
// helpers
// ---------------------------------------------------------------------------
__device__ __forceinline__ uint32_t pack_split(float v0, float v1, uint32_t& lo_out) {
    __nv_bfloat162 h2 = __floats2bfloat162_rn(v0, v1);
    float r0 = v0 - __bfloat162float(h2.x);
    float r1 = v1 - __bfloat162float(h2.y);
    __nv_bfloat162 l2 = __floats2bfloat162_rn(r0, r1);
    lo_out = *reinterpret_cast<uint32_t*>(&l2);
    return *reinterpret_cast<uint32_t*>(&h2);
}

__device__ __forceinline__ void mma16816(float d[4], const uint32_t a[4],
                                         uint32_t b0, uint32_t b1) {
    asm volatile(
        "mma.sync.aligned.m16n8k16.row.col.f32.bf16.bf16.f32 "
        "{%0,%1,%2,%3}, {%4,%5,%6,%7}, {%8,%9}, {%0,%1,%2,%3};"
        : "+f"(d[0]), "+f"(d[1]), "+f"(d[2]), "+f"(d[3])
        : "r"(a[0]), "r"(a[1]), "r"(a[2]), "r"(a[3]), "r"(b0), "r"(b1));
}

__device__ __forceinline__ void ldm4(uint32_t r[4], uint32_t saddr) {
    asm volatile("ldmatrix.sync.aligned.m8n8.x4.shared.b16 {%0,%1,%2,%3}, [%4];"
        : "=r"(r[0]), "=r"(r[1]), "=r"(r[2]), "=r"(r[3]) : "r"(saddr));
}

__device__ __forceinline__ void cp_async16(uint32_t saddr, const void* gptr) {
    asm volatile("cp.async.cg.shared.global [%0], [%1], 16;"
                 :: "r"(saddr), "l"(gptr));
}
#define CP_ASYNC_WAIT_ALL() asm volatile("cp.async.wait_all;" ::: "memory")

__device__ __forceinline__ void load_prop_idx(const void* propers_raw, int is64,
                                              int p, int P, int N, int idx[4]) {
    if (p < P) {
        if (is64) {
            longlong2 a = ((const longlong2*)propers_raw)[(size_t)p * 2];
            longlong2 b = ((const longlong2*)propers_raw)[(size_t)p * 2 + 1];
            idx[0] = (int)a.x; idx[1] = (int)a.y;
            idx[2] = (int)b.x; idx[3] = (int)b.y;
        } else {
            int4 v = ((const int4*)propers_raw)[p];
            idx[0] = v.x; idx[1] = v.y; idx[2] = v.z; idx[3] = v.w;
        }
    } else {
        idx[0] = idx[1] = idx[2] = idx[3] = 0;
    }
    #pragma unroll
    for (int j = 0; j < 4; j++) {
        int v = idx[j];
        v = v < 0 ? 0 : v;
        idx[j] = v >= N ? N - 1 : v;
    }
}

// ---------------------------------------------------------------------------
// merged prep kernel: dtype detect + weight images + answer->out copy
// blocks: 0 = detect (+copy tail); 1..64 = W1/W2; 65..192 = W0 chunks;
//         193.. = answer copy (float4)
// ---------------------------------------------------------------------------
__global__ void prep_all_kernel(const int* __restrict__ prop_words, int nwords,
                                const float* __restrict__ W0,
                                const float* __restrict__ W1,
                                const float* __restrict__ W2,
                                const float* __restrict__ answer,
                                float* __restrict__ out,
                                int n_ans)
{
    const int b = blockIdx.x;
    if (b == 0) {
        __shared__ int nz;
        if (threadIdx.x == 0) nz = 0;
        __syncthreads();
        for (int i = 1 + 2 * threadIdx.x; i < nwords; i += 2 * blockDim.x) {
            if (prop_words[i] != 0) { atomicOr(&nz, 1); break; }
        }
        __syncthreads();
        if (threadIdx.x == 0) {
            g_idx64 = (nz == 0) ? 1 : 0;
            // scalar tail of the answer copy (n_ans % 4 elements)
            for (int i = n_ans & ~3; i < n_ans; i++) out[i] = answer[i];
        }
    } else if (b <= 64) {
        int idx = (b - 1) * 256 + threadIdx.x;
        int l = idx >> 13;
        int r = idx & 8191;
        int n = r >> 6;
        int k = (r & 63) * 2;
        const float* W = l ? W2 : W1;
        float v0 = W[(size_t)k * DD + n];
        float v1 = W[(size_t)(k + 1) * DD + n];
        uint32_t lo, hi = pack_split(v0, v1, lo);
        uint32_t off = (uint32_t)n * PITCH_B + (uint32_t)k * 2;
        *(uint32_t*)(g_Bimg + (l * 2 + 0) * IMG_BYTES + off) = hi;
        *(uint32_t*)(g_Bimg + (l * 2 + 1) * IMG_BYTES + off) = lo;
    } else if (b <= 192) {
        int idx = (b - 65) * 256 + threadIdx.x;
        int a = idx >> 13;
        int r = idx & 8191;
        int n = r >> 6;
        int k = (r & 63) * 2;
        float v0 = W0[(size_t)(a * 128 + k) * DD + n];
        float v1 = W0[(size_t)(a * 128 + k + 1) * DD + n];
        uint32_t lo, hi = pack_split(v0, v1, lo);
        uint32_t off = (uint32_t)n * PITCH_B + (uint32_t)k * 2;
        *(uint32_t*)(g_B0img + (a * 2 + 0) * IMG_BYTES + off) = hi;
        *(uint32_t*)(g_B0img + (a * 2 + 1) * IMG_BYTES + off) = lo;
    } else {
        int i = (b - 193) * 256 + threadIdx.x;     // float4 index
        int nv4 = n_ans >> 2;
        if (i < nv4)
            ((float4*)out)[i] = ((const float4*)answer)[i];
    }
}

// ---------------------------------------------------------------------------
// GEMM layer: per warp 32 rows x 32 cols, 3-term bf16 split (R13 form).
// ---------------------------------------------------------------------------
__device__ __forceinline__ void gemm_layer(
    float D[2][4][4],
    uint32_t aHi0, uint32_t aHi1, uint32_t aLo0, uint32_t aLo1,
    uint32_t bHi0, uint32_t bHi1, uint32_t bLo0, uint32_t bLo1)
{
    #pragma unroll
    for (int mt = 0; mt < 2; mt++)
        #pragma unroll
        for (int nt = 0; nt < 4; nt++)
            #pragma unroll
            for (int j = 0; j < 4; j++) D[mt][nt][j] = 0.f;

    #pragma unroll
    for (int ks = 0; ks < 8; ks++) {
        const uint32_t kb = ks * 32;
        uint32_t ah[2][4], al[2][4];
        ldm4(ah[0], aHi0 + kb);
        ldm4(ah[1], aHi1 + kb);
        ldm4(al[0], aLo0 + kb);
        ldm4(al[1], aLo1 + kb);
        #pragma unroll
        for (int ntp = 0; ntp < 2; ntp++) {
            uint32_t bh[4], bl[4];
            ldm4(bh, (ntp ? bHi1 : bHi0) + kb);
            ldm4(bl, (ntp ? bLo1 : bLo0) + kb);
            #pragma unroll
            for (int mt = 0; mt < 2; mt++) {
                #pragma unroll
                for (int sub = 0; sub < 2; sub++) {
                    float* d = D[mt][ntp * 2 + sub];
                    mma16816(d, ah[mt], bh[sub], bh[2 + sub]);
                    mma16816(d, ah[mt], bl[sub], bl[2 + sub]);
                    mma16816(d, al[mt], bh[sub], bh[2 + sub]);
                }
            }
        }
    }
}

// ---------------------------------------------------------------------------
// Kernel A (tensor-core): E[a][atom][j] via bf16-split MMA.
// one block = 64 atoms x ONE chunk; grid=(ceil(N/64), 4), 2/SM.
// B-image copy via cp.async, overlapped with the enc load+pack.
// ---------------------------------------------------------------------------
#define EA_SIZE 17408
#define E_A_HI  0
#define E_A_LO  EA_SIZE
#define E_B_HI  (2 * EA_SIZE)
#define E_SMEM  (2 * EA_SIZE + 2 * IMG_BYTES)   // 104448

__global__ void __launch_bounds__(256, 2) precompute_E_mma_kernel(
    const float* __restrict__ enc,
    int N)
{
    extern __shared__ char sm[];
    const int tid = threadIdx.x;
    const int w   = tid >> 5;
    const int t   = tid & 31;
    const int wr  = w >> 2;
    const int wc  = w & 3;
    const int a     = blockIdx.y;
    const int atom0 = blockIdx.x * 64;

    const uint32_t sb = (uint32_t)__cvta_generic_to_shared(sm);

    // async B-image copy (hi+lo, 69632 B) -- overlaps with enc pack below
    {
        const char* src = (const char*)(g_B0img + (size_t)(a * 2) * IMG_BYTES);
        #pragma unroll
        for (int i = tid; i < 2 * IMG_BYTES / 16; i += 256)
            cp_async16(sb + E_B_HI + (uint32_t)i * 16, src + (size_t)i * 16);
    }
    // load + split enc tile: 64 rows x 128 cols (runs while cp.async streams B)
    #pragma unroll
    for (int it = 0; it < 8; it++) {
        int idx = tid + it * 256;
        int row = idx >> 5;
        int col = (idx & 31) * 4;
        int atom = atom0 + row;
        float4 v = make_float4(0.f, 0.f, 0.f, 0.f);
        if (atom < N) v = *(const float4*)(enc + (size_t)atom * DD + col);
        uint32_t lo0, hi0 = pack_split(v.x, v.y, lo0);
        uint32_t lo1, hi1 = pack_split(v.z, v.w, lo1);
        uint32_t o = (uint32_t)row * PITCH_B + (uint32_t)col * 2;
        *(uint32_t*)(sm + E_A_HI + o)     = hi0;
        *(uint32_t*)(sm + E_A_HI + o + 4) = hi1;
        *(uint32_t*)(sm + E_A_LO + o)     = lo0;
        *(uint32_t*)(sm + E_A_LO + o + 4) = lo1;
    }
    CP_ASYNC_WAIT_ALL();
    __syncthreads();

    const int lseg = t >> 3;
    const uint32_t lane_off = (uint32_t)((t & 7) + (lseg & 1) * 8) * PITCH_B
                            + (uint32_t)(lseg >> 1) * 16;

    const uint32_t aHi0 = sb + E_A_HI + (uint32_t)(wr * 32 +  0) * PITCH_B + lane_off;
    const uint32_t aHi1 = sb + E_A_HI + (uint32_t)(wr * 32 + 16) * PITCH_B + lane_off;
    const uint32_t aLo0 = aHi0 + EA_SIZE;
    const uint32_t aLo1 = aHi1 + EA_SIZE;
    const uint32_t bHi0 = sb + E_B_HI + (uint32_t)(wc * 32 +  0) * PITCH_B + lane_off;
    const uint32_t bHi1 = sb + E_B_HI + (uint32_t)(wc * 32 + 16) * PITCH_B + lane_off;
    const uint32_t bLo0 = bHi0 + IMG_BYTES;
    const uint32_t bLo1 = bHi1 + IMG_BYTES;

    float D[2][4][4];
    gemm_layer(D, aHi0, aHi1, aLo0, aLo1, bHi0, bHi1, bLo0, bLo1);

    #pragma unroll
    for (int mt = 0; mt < 2; mt++) {
        const int row = wr * 32 + mt * 16 + (t >> 2);
        #pragma unroll
        for (int nt = 0; nt < 4; nt++) {
            const int col = wc * 32 + nt * 8 + (t & 3) * 2;
            int atomA = atom0 + row;
            int atomB = atomA + 8;
            if (atomA < N) {
                float2* p = (float2*)(g_E + ((size_t)a * N + atomA) * DD + col);
                *p = make_float2(D[mt][nt][0], D[mt][nt][1]);
            }
            if (atomB < N) {
                float2* p = (float2*)(g_E + ((size_t)a * N + atomB) * DD + col);
                *p = make_float2(D[mt][nt][2], D[mt][nt][3]);
            }
        }
    }
}

// ---------------------------------------------------------------------------
// Main fused kernel (PERSISTENT): 512 threads = FOUR independent 4-warp
// quarters, deterministically staggered to anti-phase their MMA bursts.
// Per-quarter misc is parity double-buffered -> 5 barriers/tile.
// ---------------------------------------------------------------------------
#define A_SIZE_Q 8704                      // 32 * 272 (one term, one quarter)
#define W_SM     (8 * A_SIZE_Q)            // 69632 (4 quarters x hi/lo)
#define MISC_OFF (W_SM + 4 * IMG_BYTES)    // 208896
#define MISC_FLOATS 3260
#define SMEM_TOTAL (MISC_OFF + MISC_FLOATS * 4)   // 221936

__global__ void __launch_bounds__(512, 1) propers_kernel(
    const float* __restrict__ coords,
    const void* __restrict__ propers_raw,
    const float* __restrict__ t_arr,
    const float* __restrict__ W0,
    const float* __restrict__ b0,
    const float* __restrict__ b1,
    const float* __restrict__ b2,
    const float* __restrict__ W3,
    const float* __restrict__ b3,
    float* __restrict__ out,
    int N, int P)
{
    extern __shared__ char smem_raw[];

    float* m    = (float*)(smem_raw + MISC_OFF);
    float* vb1  = m;                // 128
    float* vb2  = m + 128;          // 128
    float* vwt  = m + 256;          // 128
    float* vws  = m + 384;
    float* vwc  = m + 512;
    float* vwd  = m + 640;
    float* vb0  = m + 768;
    float* sW3  = m + 896;          // 256
    float* vb3  = m + 1152;         // 2 (+2 pad)
    float* stv  = m + 1156;         // 4

    const int tid  = threadIdx.x;
    const int w    = tid >> 5;
    const int t    = tid & 31;
    const int q    = w >> 2;          // quarter 0..3
    const int wc   = w & 3;           // col group (0..3)
    const int tid_q = tid & 127;
    const int is64 = g_idx64;

    // per-quarter misc, parity double-buffered (256 floats per parity)
    float* qmbase = m + 1160 + q * 512;

    const uint32_t sb = (uint32_t)__cvta_generic_to_shared(smem_raw);

    // ---- one-time setup (all 512 threads); W-image copy via cp.async ----
    {
        const char* src = (const char*)g_Bimg;
        for (int i = tid; i < 4 * IMG_BYTES / 16; i += 512)
            cp_async16(sb + W_SM + (uint32_t)i * 16, src + (size_t)i * 16);
    }
    if (tid < 128) {
        vwt[tid] = W0[(size_t)512 * DD + tid];
        vws[tid] = W0[(size_t)513 * DD + tid];
        vwc[tid] = W0[(size_t)514 * DD + tid];
        vwd[tid] = W0[(size_t)515 * DD + tid];
        vb0[tid] = b0[tid];
        vb1[tid] = b1[tid];
        vb2[tid] = b2[tid];
    } else if (tid < 256) {
        int i = tid - 128;
        if (i < 2)  vb3[i] = b3[i];
        if (i < TT) stv[i] = t_arr[i];
    } else if (tid < 512) {
        int i = tid - 256;
        if (i < 256) sW3[i] = W3[i];
    }
    CP_ASYNC_WAIT_ALL();
    __syncthreads();

    // named barrier for this quarter (ids 1..4), 128 threads each
    #define QBAR() asm volatile("bar.sync %0, %1;" :: "r"(q + 1), "r"(128) : "memory")

    // ---- deterministic stagger: anti-phase the 4 quarters' MMA bursts ----
    if (q) __nanosleep(3000u * (uint32_t)q);

    // ---- ldmatrix lane addressing ----
    const int lseg = t >> 3;
    const uint32_t lane_off = (uint32_t)((t & 7) + (lseg & 1) * 8) * PITCH_B
                            + (uint32_t)(lseg >> 1) * 16;

    const uint32_t aBase = sb + (uint32_t)(q * 2 * A_SIZE_Q);
    const uint32_t aHi0 = aBase + lane_off;                       // rows 0..15
    const uint32_t aHi1 = aBase + 16u * PITCH_B + lane_off;       // rows 16..31
    const uint32_t aLo0 = aHi0 + A_SIZE_Q;
    const uint32_t aLo1 = aHi1 + A_SIZE_Q;

    const uint32_t bW = sb + W_SM + (uint32_t)(wc * 32) * PITCH_B + lane_off;
    const uint32_t b1Hi0 = bW;
    const uint32_t b1Hi1 = bW + 16u * PITCH_B;
    const uint32_t b1Lo0 = b1Hi0 + IMG_BYTES;
    const uint32_t b1Lo1 = b1Hi1 + IMG_BYTES;
    const uint32_t b2Hi0 = b1Hi0 + 2 * IMG_BYTES;
    const uint32_t b2Hi1 = b1Hi1 + 2 * IMG_BYTES;
    const uint32_t b2Lo0 = b1Lo0 + 2 * IMG_BYTES;
    const uint32_t b2Lo1 = b1Lo1 + 2 * IMG_BYTES;

    char* const Araw = smem_raw + q * 2 * A_SIZE_Q;

    const int n_qt    = (P + 7) >> 3;             // 8-proper quarter-tiles
    const int stream  = blockIdx.x * 4 + q;
    const int stride  = gridDim.x * 4;

    // per-thread pack assignment (fixed across tiles)
    const int lp = tid_q >> 4;        // proper within tile (0..7)
    const int u  = tid_q & 15;        // 8-col chunk (cols u*8 .. u*8+7)

    int parity = 0;

    for (int qt = stream; qt < n_qt; qt += stride, parity ^= 1) {
        const int pbase = qt * 8;

        float* qm    = qmbase + parity * 256;
        float* ssin  = qm;                // 32
        float* scos  = qm + 32;
        float* sdl   = qm + 64;
        float* sdh   = qm + 96;           // 96
        float* sdelta= qm + 192;          // 64

        // ---- prologue: direct index loads + early E prefetch (registers) ----
        int pidx[4];
        load_prop_idx(propers_raw, is64, pbase + lp, P, N, pidx);
        const float* E0 = g_E + (size_t)pidx[0] * DD + u * 8;
        const float* E1 = g_E + ((size_t)N * 1 + pidx[1]) * DD + u * 8;
        const float* E2 = g_E + ((size_t)N * 2 + pidx[2]) * DD + u * 8;
        const float* E3 = g_E + ((size_t)N * 3 + pidx[3]) * DD + u * 8;
        float4 e0a = *(const float4*)(E0);
        float4 e0b = *(const float4*)(E0 + 4);
        float4 e1a = *(const float4*)(E1);
        float4 e1b = *(const float4*)(E1 + 4);
        float4 e2a = *(const float4*)(E2);
        float4 e2b = *(const float4*)(E2 + 4);
        float4 e3a = *(const float4*)(E3);
        float4 e3b = *(const float4*)(E3 + 4);

        // ---- geometry (32 threads), sdelta zero (64 threads) ----
        if (tid_q < 32) {
            const int row = tid_q;
            const int glp = row >> 2;
            const int tt  = row & 3;
            int gidx[4];
            load_prop_idx(propers_raw, is64, pbase + glp, P, N, gidx);

            const float* c0 = coords + (size_t)(gidx[0] * TT + tt) * 3;
            const float* c1 = coords + (size_t)(gidx[1] * TT + tt) * 3;
            const float* c2 = coords + (size_t)(gidx[2] * TT + tt) * 3;
            const float* c3 = coords + (size_t)(gidx[3] * TT + tt) * 3;

            float c0x = c0[0], c0y = c0[1], c0z = c0[2];
            float c1x = c1[0], c1y = c1[1], c1z = c1[2];
            float c2x = c2[0], c2y = c2[1], c2z = c2[2];
            float c3x = c3[0], c3y = c3[1], c3z = c3[2];

            float u1x = c1x - c0x, u1y = c1y - c0y, u1z = c1z - c0z;
            float u2x = c2x - c1x, u2y = c2y - c1y, u2z = c2z - c1z;
            float u3x = c3x - c2x, u3y = c3y - c2y, u3z = c3z - c2z;

            float ax = u1y * u2z - u1z * u2y;
            float ay = u1z * u2x - u1x * u2z;
            float az = u1x * u2y - u1y * u2x;
            float bx = u2y * u3z - u2z * u3y;
            float by = u2z * u3x - u2x * u3z;
            float bz = u2x * u3y - u2y * u3x;

            float x   = ax * bx + ay * by + az * bz;
            float u2n = sqrtf(u2x * u2x + u2y * u2y + u2z * u2z);
            float y   = u2n * (u1x * bx + u1y * by + u1z * bz);

            float r2 = x * x + y * y;
            float s, c;
            if (r2 > 1e-30f) {
                float rinv = rsqrtf(r2);
                s = y * rinv;
                c = x * rinv;
            } else { s = 0.f; c = 1.f; }

            float drx = c0x - c3x, dry = c0y - c3y, drz = c0z - c3z;
            float dl  = sqrtf(fmaxf(drx * drx + dry * dry + drz * drz, 1e-12f));
            float inv = 1.f / dl;

            ssin[row] = s;
            scos[row] = c;
            sdl[row]  = dl;
            sdh[row * 3 + 0] = drx * inv;
            sdh[row * 3 + 1] = dry * inv;
            sdh[row * 3 + 2] = drz * inv;
        } else if (tid_q < 96) {
            sdelta[tid_q - 32] = 0.f;
        }
        QBAR();

        // ---- layer 0: E register sums + scalar feats -> split bf16 A tile ----
        {
            const int col0 = u * 8;
            float4 bbA = *(const float4*)(vb0 + col0);
            float4 bbB = *(const float4*)(vb0 + col0 + 4);
            float sAx = e0a.x + e1a.x + e2a.x + e3a.x + bbA.x;
            float sAy = e0a.y + e1a.y + e2a.y + e3a.y + bbA.y;
            float sAz = e0a.z + e1a.z + e2a.z + e3a.z + bbA.z;
            float sAw = e0a.w + e1a.w + e2a.w + e3a.w + bbA.w;
            float sBx = e0b.x + e1b.x + e2b.x + e3b.x + bbB.x;
            float sBy = e0b.y + e1b.y + e2b.y + e3b.y + bbB.y;
            float sBz = e0b.z + e1b.z + e2b.z + e3b.z + bbB.z;
            float sBw = e0b.w + e1b.w + e2b.w + e3b.w + bbB.w;
            float4 vtA = *(const float4*)(vwt + col0);
            float4 vtB = *(const float4*)(vwt + col0 + 4);
            float4 vsA = *(const float4*)(vws + col0);
            float4 vsB = *(const float4*)(vws + col0 + 4);
            float4 vcA = *(const float4*)(vwc + col0);
            float4 vcB = *(const float4*)(vwc + col0 + 4);
            float4 vdA = *(const float4*)(vwd + col0);
            float4 vdB = *(const float4*)(vwd + col0 + 4);

            #pragma unroll
            for (int tt = 0; tt < TT; tt++) {
                const int row = lp * 4 + tt;
                float tv = stv[tt];
                float sv = ssin[row];
                float cv = scos[row];
                float dv = sdl[row];
                float vA0 = sAx + tv * vtA.x + sv * vsA.x + cv * vcA.x + dv * vdA.x;
                float vA1 = sAy + tv * vtA.y + sv * vsA.y + cv * vcA.y + dv * vdA.y;
                float vA2 = sAz + tv * vtA.z + sv * vsA.z + cv * vcA.z + dv * vdA.z;
                float vA3 = sAw + tv * vtA.w + sv * vsA.w + cv * vcA.w + dv * vdA.w;
                float vB0 = sBx + tv * vtB.x + sv * vsB.x + cv * vcB.x + dv * vdB.x;
                float vB1 = sBy + tv * vtB.y + sv * vsB.y + cv * vcB.y + dv * vdB.y;
                float vB2 = sBz + tv * vtB.z + sv * vsB.z + cv * vcB.z + dv * vdB.z;
                float vB3 = sBw + tv * vtB.w + sv * vsB.w + cv * vcB.w + dv * vdB.w;
                vA0 = (vA0 > 0.f) ? vA0 : 0.001f * vA0;
                vA1 = (vA1 > 0.f) ? vA1 : 0.001f * vA1;
                vA2 = (vA2 > 0.f) ? vA2 : 0.001f * vA2;
                vA3 = (vA3 > 0.f) ? vA3 : 0.001f * vA3;
                vB0 = (vB0 > 0.f) ? vB0 : 0.001f * vB0;
                vB1 = (vB1 > 0.f) ? vB1 : 0.001f * vB1;
                vB2 = (vB2 > 0.f) ? vB2 : 0.001f * vB2;
                vB3 = (vB3 > 0.f) ? vB3 : 0.001f * vB3;
                uint4 hiv, lov;
                hiv.x = pack_split(vA0, vA1, lov.x);
                hiv.y = pack_split(vA2, vA3, lov.y);
                hiv.z = pack_split(vB0, vB1, lov.z);
                hiv.w = pack_split(vB2, vB3, lov.w);
                uint32_t o = (uint32_t)row * PITCH_B + (uint32_t)col0 * 2;
                *(uint4*)(Araw + o)            = hiv;
                *(uint4*)(Araw + A_SIZE_Q + o) = lov;
            }
        }
        QBAR();

        // ================= layer 1 =================
        float D[2][4][4];
        gemm_layer(D, aHi0, aHi1, aLo0, aLo1, b1Hi0, b1Hi1, b1Lo0, b1Lo1);

        QBAR();   // all quarter-warps done reading A before overwrite

        // ---- epilogue 1: bias + leaky, re-split into A tile ----
        {
            #pragma unroll
            for (int mt = 0; mt < 2; mt++) {
                const int r0 = mt * 16 + (t >> 2);
                #pragma unroll
                for (int nt = 0; nt < 4; nt++) {
                    const int c = wc * 32 + nt * 8 + (t & 3) * 2;
                    float bia = vb1[c], bib = vb1[c + 1];
                    float v0 = D[mt][nt][0] + bia, v1 = D[mt][nt][1] + bib;
                    float v2 = D[mt][nt][2] + bia, v3 = D[mt][nt][3] + bib;
                    v0 = (v0 > 0.f) ? v0 : 0.001f * v0;
                    v1 = (v1 > 0.f) ? v1 : 0.001f * v1;
                    v2 = (v2 > 0.f) ? v2 : 0.001f * v2;
                    v3 = (v3 > 0.f) ? v3 : 0.001f * v3;
                    uint32_t lo0, hi0 = pack_split(v0, v1, lo0);
                    uint32_t lo1, hi1 = pack_split(v2, v3, lo1);
                    uint32_t oA = (uint32_t)r0 * PITCH_B + (uint32_t)c * 2;
                    uint32_t oB = oA + 8u * PITCH_B;
                    *(uint32_t*)(Araw + oA)            = hi0;
                    *(uint32_t*)(Araw + A_SIZE_Q + oA) = lo0;
                    *(uint32_t*)(Araw + oB)            = hi1;
                    *(uint32_t*)(Araw + A_SIZE_Q + oB) = lo1;
                }
            }
        }
        QBAR();

        // ================= layer 2 =================
        gemm_layer(D, aHi0, aHi1, aLo0, aLo1, b2Hi0, b2Hi1, b2Lo0, b2Lo1);

        // ---- epilogue 2: bias+leaky, partial delta over this warp's 32 cols ----
        {
            float a0[2][2], a1[2][2];
            #pragma unroll
            for (int mt = 0; mt < 2; mt++)
                a0[mt][0] = a0[mt][1] = a1[mt][0] = a1[mt][1] = 0.f;

            #pragma unroll
            for (int mt = 0; mt < 2; mt++) {
                #pragma unroll
                for (int nt = 0; nt < 4; nt++) {
                    const int c = wc * 32 + nt * 8 + (t & 3) * 2;
                    float bia = vb2[c], bib = vb2[c + 1];
                    float v0 = D[mt][nt][0] + bia, v1 = D[mt][nt][1] + bib;
                    float v2 = D[mt][nt][2] + bia, v3 = D[mt][nt][3] + bib;
                    v0 = (v0 > 0.f) ? v0 : 0.001f * v0;
                    v1 = (v1 > 0.f) ? v1 : 0.001f * v1;
                    v2 = (v2 > 0.f) ? v2 : 0.001f * v2;
                    v3 = (v3 > 0.f) ? v3 : 0.001f * v3;
                    float w00 = sW3[c * 2 + 0], w01 = sW3[c * 2 + 1];
                    float w10 = sW3[c * 2 + 2], w11 = sW3[c * 2 + 3];
                    a0[mt][0] += v0 * w00 + v1 * w10;
                    a1[mt][0] += v0 * w01 + v1 * w11;
                    a0[mt][1] += v2 * w00 + v3 * w10;
                    a1[mt][1] += v2 * w01 + v3 * w11;
                }
            }
            #pragma unroll
            for (int off = 1; off <= 2; off <<= 1) {
                #pragma unroll
                for (int mt = 0; mt < 2; mt++) {
                    a0[mt][0] += __shfl_xor_sync(0xffffffffu, a0[mt][0], off);
                    a1[mt][0] += __shfl_xor_sync(0xffffffffu, a1[mt][0], off);
                    a0[mt][1] += __shfl_xor_sync(0xffffffffu, a0[mt][1], off);
                    a1[mt][1] += __shfl_xor_sync(0xffffffffu, a1[mt][1], off);
                }
            }
            if ((t & 3) == 0) {
                #pragma unroll
                for (int mt = 0; mt < 2; mt++) {
                    #pragma unroll
                    for (int half = 0; half < 2; half++) {
                        const int row = mt * 16 + (t >> 2) + half * 8;
                        atomicAdd(&sdelta[row * 2 + 0], a0[mt][half]);
                        atomicAdd(&sdelta[row * 2 + 1], a1[mt][half]);
                    }
                }
            }
        }
        QBAR();

        // ---- scatter (direct index reloads); NO trailing barrier (parity
        //      double-buffered misc; same-buffer reuse is 2 tiles away) ----
        if (tid_q < 32) {
            const int row = tid_q;
            const int glp = row >> 2;
            const int tt  = row & 3;
            const int p   = pbase + glp;
            if (p < P) {
                int gidx[4];
                load_prop_idx(propers_raw, is64, p, P, N, gidx);
                const float d0 = sdelta[row * 2 + 0] + vb3[0];
                const float d1 = sdelta[row * 2 + 1] + vb3[1];
                float hx = sdh[row * 3 + 0];
                float hy = sdh[row * 3 + 1];
                float hz = sdh[row * 3 + 2];
                float* o0 = out + (size_t)(gidx[0] * TT + tt) * 3;
                float* o3 = out + (size_t)(gidx[3] * TT + tt) * 3;
                atomicAdd(o0 + 0, -0.5f * d0 * hx);
                atomicAdd(o0 + 1, -0.5f * d0 * hy);
                atomicAdd(o0 + 2, -0.5f * d0 * hz);
                atomicAdd(o3 + 0,  0.5f * d1 * hx);
                atomicAdd(o3 + 1,  0.5f * d1 * hy);
                atomicAdd(o3 + 2,  0.5f * d1 * hz);
            }
        }
    }
    #undef QBAR
}

// ---------------------------------------------------------------------------
extern "C" void kernel_launch(void* const* d_in, const int* in_sizes, int n_in,
                              void* d_out, int out_size)
{
    const float* coords  = (const float*)d_in[0];
    const void*  propers = d_in[1];
    const float* enc     = (const float*)d_in[2];
    const float* t_arr   = (const float*)d_in[3];
    const float* answer  = (const float*)d_in[4];
    const float* W0      = (const float*)d_in[5];
    const float* b0      = (const float*)d_in[6];
    const float* W1      = (const float*)d_in[7];
    const float* b1      = (const float*)d_in[8];
    const float* W2      = (const float*)d_in[9];
    const float* b2      = (const float*)d_in[10];
    const float* W3      = (const float*)d_in[11];
    const float* b3      = (const float*)d_in[12];
    float*       out     = (float*)d_out;

    const int N = in_sizes[2] / DD;
    const int P = in_sizes[1] / 4;
    const int n_ans = in_sizes[4];

    int dev = 0, sms = 148;
    cudaGetDevice(&dev);
    cudaDeviceGetAttribute(&sms, cudaDevAttrMultiProcessorCount, dev);

    int nwords = in_sizes[1] < 4096 ? in_sizes[1] : 4096;
    const int nb_copy = ((n_ans >> 2) + 255) / 256;
    prep_all_kernel<<<193 + nb_copy, 256>>>((const int*)propers, nwords,
                                            W0, W1, W2, answer, out, n_ans);

    cudaFuncSetAttribute(precompute_E_mma_kernel,
                         cudaFuncAttributeMaxDynamicSharedMemorySize, E_SMEM);
    precompute_E_mma_kernel<<<dim3((N + 63) / 64, 4), 256, E_SMEM>>>(enc, N);

    cudaFuncSetAttribute(propers_kernel,
                         cudaFuncAttributeMaxDynamicSharedMemorySize, SMEM_TOTAL);
    propers_kernel<<<sms, 512, SMEM_TOTAL>>>(
        coords, propers, t_arr, W0, b0, b1, b2, W3, b3, out, N, P);
}